// round 14
// baseline (speedup 1.0000x reference)
#include <cuda_runtime.h>
#include <cuda_bf16.h>
#include <math.h>
#include <stdint.h>

#define NITER 25
#define SYN_KC 8

// ----------------- static device scratch -----------------
__device__ float g_kv[32 * 256 * 512];       // (b,s,d) post-LN
__device__ float g_KV[32 * 256 * 1024];      // (b,s,[K|V])
__device__ float g_WqqT[512 * 512];          // [e][n]
__device__ float g_bqq[512];
__device__ float g_Was[512 * 4096];          // aoT @ syn_w_top [d][j]
__device__ float g_synb2[4096];
__device__ float g_tp1wt[2048 * 3200];       // [d][m*128+h]
__device__ float g_tp2wt[2048 * 128];        // [d][h*2+o]
__device__ float g_act[2][32 * 2048];        // double-buffered
__device__ float g_trace[32 * 2048 * 25];    // ring on last dim
__device__ float g_daa[2][32 * 512];
__device__ float g_dba[2][32 * 512];
__device__ float g_dao[2][32 * 512];
__device__ float g_dbo[2][32 * 512];
__device__ float g_ra[512];
__device__ float g_ro[512];
__device__ float g_attn[32 * 512];
__device__ float g_synp[SYN_KC * 32 * 4096]; // split-K partials
__device__ float g_pred[32 * 1000];

// ----------------- helpers -----------------
__device__ __forceinline__ float warpSum(float v) {
#pragma unroll
    for (int o = 16; o; o >>= 1) v += __shfl_down_sync(0xffffffffu, v, o);
    return v;
}
__device__ __forceinline__ float warpMax(float v) {
#pragma unroll
    for (int o = 16; o; o >>= 1) v = fmaxf(v, __shfl_down_sync(0xffffffffu, v, o));
    return v;
}
template<int NW>
__device__ __forceinline__ float blockSumAll(float v, volatile float* red) {
    float s = warpSum(v);
    __syncthreads();
    if ((threadIdx.x & 31) == 0) red[threadIdx.x >> 5] = s;
    __syncthreads();
    float t = 0.f;
#pragma unroll
    for (int i = 0; i < NW; i++) t += red[i];
    return t;
}
template<int NW>
__device__ __forceinline__ float blockMaxAll(float v, volatile float* red) {
    float s = warpMax(v);
    __syncthreads();
    if ((threadIdx.x & 31) == 0) red[threadIdx.x >> 5] = s;
    __syncthreads();
    float t = -3.4e38f;
#pragma unroll
    for (int i = 0; i < NW; i++) t = fmaxf(t, red[i]);
    return t;
}
__device__ __forceinline__ float sigm(float x) { return 1.f / (1.f + expf(-x)); }

#define MMA_TF32(c, a, b)                                               \
    asm volatile(                                                       \
        "mma.sync.aligned.m16n8k8.row.col.f32.tf32.tf32.f32 "           \
        "{%0,%1,%2,%3}, {%4,%5,%6,%7}, {%8,%9}, {%0,%1,%2,%3};"         \
        : "+f"((c)[0]), "+f"((c)[1]), "+f"((c)[2]), "+f"((c)[3])        \
        : "r"((a)[0]), "r"((a)[1]), "r"((a)[2]), "r"((a)[3]),           \
          "r"((b)[0]), "r"((b)[1]))

// ----------------- 3xTF32 big GEMM (preamble): 64m x 128n tile -----------------
// amode 0: A row-major. amode 1: A col-major (lda=M). amode 2: x tensor.
__global__ void __launch_bounds__(256) k_tgemm(
    const float* __restrict__ A, const float* __restrict__ Bm,
    const float* __restrict__ bias, float* __restrict__ Cm,
    int M, int N, int K, int ldc, int amode, int transB) {
    __shared__ float As[32][68];
    __shared__ float Bs[32][132];
    int m0 = blockIdx.y * 64, n0 = blockIdx.x * 128;
    int tid = threadIdx.x;
    int w = tid >> 5, l = tid & 31;
    int wm = w >> 2, wn = w & 3;
    const unsigned MASK = 0xffffe000u;
    float acc[2][4][4] = {};
    for (int k0 = 0; k0 < K; k0 += 32) {
        if (amode == 0) {
#pragma unroll
            for (int r = 0; r < 2; r++) {
                int idx = tid + r * 256;
                int m = idx >> 3;
                int k4 = (idx & 7) * 4;
                float4 v = *(const float4*)&A[(size_t)(m0 + m) * K + k0 + k4];
                As[k4 + 0][m] = v.x; As[k4 + 1][m] = v.y;
                As[k4 + 2][m] = v.z; As[k4 + 3][m] = v.w;
            }
        } else if (amode == 1) {
#pragma unroll
            for (int r = 0; r < 2; r++) {
                int idx = tid + r * 256;
                int k = idx >> 4;
                int m4 = (idx & 15) * 4;
                float4 v = *(const float4*)&A[(size_t)(k0 + k) * M + m0 + m4];
                *(float4*)&As[k][m4] = v;
            }
        } else {
            int b0 = m0 >> 8, s0 = m0 & 255;
#pragma unroll
            for (int r = 0; r < 2; r++) {
                int idx = tid + r * 256;
                int k = idx >> 4;
                int m4 = (idx & 15) * 4;
                float4 v = *(const float4*)&A[(size_t)b0 * 131072 + (size_t)(k0 + k) * 256 + s0 + m4];
                *(float4*)&As[k][m4] = v;
            }
        }
        if (!transB) {
#pragma unroll
            for (int r = 0; r < 4; r++) {
                int idx = tid + r * 256;
                int k = idx >> 5;
                int n4 = (idx & 31) * 4;
                float4 v = *(const float4*)&Bm[(size_t)(k0 + k) * N + n0 + n4];
                *(float4*)&Bs[k][n4] = v;
            }
        } else {
#pragma unroll
            for (int r = 0; r < 4; r++) {
                int idx = tid + r * 256;
                int n = idx >> 3;
                int k4 = (idx & 7) * 4;
                float4 v = *(const float4*)&Bm[(size_t)(n0 + n) * K + k0 + k4];
                Bs[k4 + 0][n] = v.x; Bs[k4 + 1][n] = v.y;
                Bs[k4 + 2][n] = v.z; Bs[k4 + 3][n] = v.w;
            }
        }
        __syncthreads();
#pragma unroll
        for (int ks = 0; ks < 4; ks++) {
            int kb = ks * 8;
            unsigned bh[4][2], bl[4][2];
#pragma unroll
            for (int nt = 0; nt < 4; nt++) {
                int col = wn * 32 + nt * 8 + (l >> 2);
                float b0 = Bs[kb + (l & 3)][col];
                float b1 = Bs[kb + (l & 3) + 4][col];
                unsigned u0 = __float_as_uint(b0) & MASK;
                unsigned u1 = __float_as_uint(b1) & MASK;
                bh[nt][0] = u0;
                bh[nt][1] = u1;
                bl[nt][0] = __float_as_uint(b0 - __uint_as_float(u0));
                bl[nt][1] = __float_as_uint(b1 - __uint_as_float(u1));
            }
#pragma unroll
            for (int mt = 0; mt < 2; mt++) {
                int row = wm * 32 + mt * 16 + (l >> 2);
                int ak = kb + (l & 3);
                float a0 = As[ak][row];
                float a1 = As[ak][row + 8];
                float a2 = As[ak + 4][row];
                float a3 = As[ak + 4][row + 8];
                unsigned ah[4], al[4];
                ah[0] = __float_as_uint(a0) & MASK;
                ah[1] = __float_as_uint(a1) & MASK;
                ah[2] = __float_as_uint(a2) & MASK;
                ah[3] = __float_as_uint(a3) & MASK;
                al[0] = __float_as_uint(a0 - __uint_as_float(ah[0]));
                al[1] = __float_as_uint(a1 - __uint_as_float(ah[1]));
                al[2] = __float_as_uint(a2 - __uint_as_float(ah[2]));
                al[3] = __float_as_uint(a3 - __uint_as_float(ah[3]));
#pragma unroll
                for (int nt = 0; nt < 4; nt++) {
                    MMA_TF32(acc[mt][nt], ah, bh[nt]);
                    MMA_TF32(acc[mt][nt], al, bh[nt]);
                    MMA_TF32(acc[mt][nt], ah, bl[nt]);
                }
            }
        }
        __syncthreads();
    }
#pragma unroll
    for (int mt = 0; mt < 2; mt++)
#pragma unroll
        for (int nt = 0; nt < 4; nt++) {
            int r = m0 + wm * 32 + mt * 16 + (l >> 2);
            int c = n0 + wn * 32 + nt * 8 + (l & 3) * 2;
            float b0 = bias ? bias[c] : 0.f;
            float b1 = bias ? bias[c + 1] : 0.f;
            *(float2*)&Cm[(size_t)r * ldc + c] =
                make_float2(acc[mt][nt][0] + b0, acc[mt][nt][1] + b1);
            *(float2*)&Cm[(size_t)(r + 8) * ldc + c] =
                make_float2(acc[mt][nt][2] + b0, acc[mt][nt][3] + b1);
        }
}

// ----------------- LN over rows of 512 (preamble) -----------------
__global__ void k_ln512(float* __restrict__ buf, const float* __restrict__ g,
                        const float* __restrict__ bb) {
    __shared__ float red[8];
    float* p = buf + (size_t)blockIdx.x * 512;
    int tid = threadIdx.x;
    float v0 = p[tid], v1 = p[tid + 256];
    float mean = blockSumAll<8>(v0 + v1, red) * (1.f / 512.f);
    float d0 = v0 - mean, d1 = v1 - mean;
    float var = blockSumAll<8>(d0 * d0 + d1 * d1, red) * (1.f / 512.f);
    float inv = rsqrtf(var + 1e-5f);
    p[tid] = d0 * inv * g[tid] + bb[tid];
    p[tid + 256] = d1 * inv * g[tid + 256] + bb[tid + 256];
}

// ----------------- misc init mega-kernel (preamble) -----------------
__device__ __forceinline__ void transpose_tile(const float* __restrict__ in,
                                               float* __restrict__ out,
                                               int R, int Cc, int tr, int tc) {
    __shared__ float t[32][33];
    int tid = threadIdx.x;
    int lx = tid & 31, ly = tid >> 5;
    int r0 = tr * 32, c0 = tc * 32;
#pragma unroll
    for (int i = ly; i < 32; i += 8)
        t[i][lx] = in[(size_t)(r0 + i) * Cc + c0 + lx];
    __syncthreads();
#pragma unroll
    for (int i = ly; i < 32; i += 8)
        out[(size_t)(c0 + i) * R + r0 + lx] = t[lx][i];
}

__global__ void __launch_bounds__(256) k_misc(
    const float* __restrict__ q_w, const float* __restrict__ q_b,
    const float* __restrict__ attn_in_w, const float* __restrict__ attn_in_b,
    const float* __restrict__ attn_out_b,
    const float* __restrict__ syn_w, const float* __restrict__ syn_b,
    const float* __restrict__ tp1_w, const float* __restrict__ tp2_w,
    const float* __restrict__ sas, const float* __restrict__ st,
    const int* __restrict__ ol, const int* __restrict__ orr,
    const float* __restrict__ da, const float* __restrict__ dco) {
    int blk = blockIdx.x;
    int tid = threadIdx.x;
    if (blk < 64) {
        __shared__ float As[16][65];
        __shared__ float Bs[16][65];
        int m0 = (blk >> 3) * 64, n0 = (blk & 7) * 64;
        int tx = tid % 16, ty = tid / 16;
        float acc[4][4] = {};
        for (int k0 = 0; k0 < 512; k0 += 16) {
#pragma unroll
            for (int p = 0; p < 4; p++) {
                int m = ty + p * 16;
                As[tx][m] = attn_in_w[(size_t)(m0 + m) * 512 + k0 + tx];
                Bs[tx][m] = q_w[(size_t)(n0 + m) * 512 + k0 + tx];
            }
            __syncthreads();
#pragma unroll
            for (int k = 0; k < 16; k++) {
                float a[4], b[4];
#pragma unroll
                for (int i = 0; i < 4; i++) a[i] = As[k][ty * 4 + i];
#pragma unroll
                for (int j = 0; j < 4; j++) b[j] = Bs[k][tx * 4 + j];
#pragma unroll
                for (int i = 0; i < 4; i++)
#pragma unroll
                    for (int j = 0; j < 4; j++) acc[i][j] += a[i] * b[j];
            }
            __syncthreads();
        }
#pragma unroll
        for (int i = 0; i < 4; i++)
#pragma unroll
            for (int j = 0; j < 4; j++)
                g_WqqT[(size_t)(m0 + ty * 4 + i) * 512 + n0 + tx * 4 + j] = acc[i][j];
    } else if (blk < 6464) {
        int tIdx = blk - 64;
        transpose_tile(tp1_w, g_tp1wt, 3200, 2048, tIdx / 64, tIdx % 64);
    } else if (blk < 6720) {
        int tIdx = blk - 6464;
        transpose_tile(tp2_w, g_tp2wt, 128, 2048, tIdx / 64, tIdx % 64);
    } else if (blk < 6722) {
        int e = (blk - 6720) * 256 + tid;
        float s = attn_in_b[e];
        for (int d = 0; d < 512; d++) s += q_b[d] * attn_in_w[(size_t)e * 512 + d];
        g_bqq[e] = s;
    } else if (blk < 6738) {
        int j = (blk - 6722) * 256 + tid;
        float s = syn_b[j];
        for (int e = 0; e < 512; e++) s += attn_out_b[e] * syn_w[(size_t)e * 4096 + j];
        g_synb2[j] = s;
    } else if (blk < 6994) {
        int i = (blk - 6738) * 256 + tid;
        int d = i & 2047;
        g_act[1][i] = sas[d];
#pragma unroll
        for (int s = 0; s < 25; s++) g_trace[(size_t)i * 25 + s] = st[d * 25 + s];
    } else {
        int i = (blk - 6994) * 256 + tid;
        int n = i & 511;
        g_daa[0][i] = 0.f;
        g_dba[0][i] = 0.f;
        g_dao[0][i] = sas[ol[n]] * sas[orr[n]];
        g_dbo[0][i] = 1.f;
        if (i < 512) {
            g_ra[i] = expf(-fminf(fmaxf(da[i], 0.f), 15.f));
            g_ro[i] = expf(-fminf(fmaxf(dco[i], 0.f), 15.f));
        }
    }
}

// ----------------- loop phase 1: syncA + q + attention -----------------
__global__ void __launch_bounds__(256) k_phase1(const int* __restrict__ il,
                                                const int* __restrict__ ir, int p) {
    int b = blockIdx.x >> 3, h = blockIdx.x & 7;
    __shared__ float sa[512];
    __shared__ float qh[64];
    __shared__ float pr[256];
    __shared__ float red[8];
    __shared__ float av[4][64];
    int tid = threadIdx.x;
    const float* act = g_act[1 - p];
#pragma unroll
    for (int r = 0; r < 2; r++) {
        int n = tid + r * 256;
        float ra = g_ra[n];
        float prod = act[b * 2048 + il[n]] * act[b * 2048 + ir[n]];
        float daa = ra * g_daa[p][b * 512 + n] + prod;
        float dba = ra * g_dba[p][b * 512 + n] + 1.f;
        if (h == 0) {
            g_daa[1 - p][b * 512 + n] = daa;
            g_dba[1 - p][b * 512 + n] = dba;
        }
        sa[n] = daa * rsqrtf(dba);
    }
    __syncthreads();
    {
        int e = tid >> 2, qd = tid & 3;
        const float* wr = g_WqqT + (size_t)(h * 64 + e) * 512 + qd * 128;
        const float* sap = sa + qd * 128;
        float acc = 0.f;
#pragma unroll
        for (int k = 0; k < 128; k += 4) {
            float4 w = *(const float4*)&wr[k];
            acc += sap[k] * w.x + sap[k + 1] * w.y + sap[k + 2] * w.z + sap[k + 3] * w.w;
        }
        acc += __shfl_down_sync(0xffffffffu, acc, 2);
        acc += __shfl_down_sync(0xffffffffu, acc, 1);
        if (qd == 0) qh[e] = acc + g_bqq[h * 64 + e];
    }
    __syncthreads();
    const float* Kp = g_KV + ((size_t)(b * 256 + tid)) * 1024 + h * 64;
    float sc = 0.f;
#pragma unroll
    for (int d4 = 0; d4 < 64; d4 += 4) {
        float4 kvv = *(const float4*)&Kp[d4];
        sc += qh[d4] * kvv.x + qh[d4 + 1] * kvv.y + qh[d4 + 2] * kvv.z + qh[d4 + 3] * kvv.w;
    }
    sc *= 0.125f;
    float mall = blockMaxAll<8>(sc, red);
    float e1 = expf(sc - mall);
    float ssum = blockSumAll<8>(e1, red);
    pr[tid] = e1 / ssum;
    __syncthreads();
    int dd = tid & 63, qq = tid >> 6;
    const float* Vp = g_KV + ((size_t)(b * 256 + qq * 64)) * 1024 + 512 + h * 64 + dd;
    float acc = 0.f;
#pragma unroll 8
    for (int j = 0; j < 64; j++) acc += pr[qq * 64 + j] * Vp[(size_t)j * 1024];
    av[qq][dd] = acc;
    __syncthreads();
    if (tid < 64)
        g_attn[b * 512 + h * 64 + tid] = av[0][tid] + av[1][tid] + av[2][tid] + av[3][tid];
}

// ----------------- loop phase 2: 3xTF32 syn GEMM, split-K x8 -----------------
// grid (64 nblk of 64, 8 kc of 320). Block: 256 thr = 8 warps; warp covers
// 32 m (all batches) x 8 n. A (32x320) staged to smem once; W straight from L2.
__global__ void __launch_bounds__(256) k_syngemm(const float* __restrict__ syn_w, int p) {
    __shared__ float As[320 * 33];  // [k][b], padded
    int tid = threadIdx.x;
    int w = tid >> 5, l = tid & 31;
    int n0 = blockIdx.x * 64;
    int kc = blockIdx.y;
    const float* act = g_act[1 - p];
    const unsigned MASK = 0xffffe000u;
    // stage A: 32 b x 320 k (float4 over k; 512 is 4-aligned so branch per group)
    for (int idx = tid; idx < 2560; idx += 256) {
        int b = idx / 80, kq = (idx % 80) * 4;
        int kg = kc * 320 + kq;
        float4 v = (kg < 512) ? *(const float4*)&g_attn[b * 512 + kg]
                              : *(const float4*)&act[b * 2048 + kg - 512];
        As[(kq + 0) * 33 + b] = v.x;
        As[(kq + 1) * 33 + b] = v.y;
        As[(kq + 2) * 33 + b] = v.z;
        As[(kq + 3) * 33 + b] = v.w;
    }
    __syncthreads();
    float acc[2][4] = {};
    int colb = n0 + w * 8;
    for (int s = 0; s < 40; s++) {
        int kg = kc * 320 + s * 8;
        const float* Wr = ((kg < 512) ? g_Was : syn_w) + (size_t)kg * 4096 + colb;
        // B fragment (8 cols)
        float b0 = Wr[(size_t)(l & 3) * 4096 + (l >> 2)];
        float b1 = Wr[(size_t)((l & 3) + 4) * 4096 + (l >> 2)];
        unsigned bh[2], bl[2];
        bh[0] = __float_as_uint(b0) & MASK;
        bh[1] = __float_as_uint(b1) & MASK;
        bl[0] = __float_as_uint(b0 - __uint_as_float(bh[0]));
        bl[1] = __float_as_uint(b1 - __uint_as_float(bh[1]));
        int sk = s * 8;
#pragma unroll
        for (int mt = 0; mt < 2; mt++) {
            int row = mt * 16 + (l >> 2);
            int ak = sk + (l & 3);
            float a0 = As[ak * 33 + row];
            float a1 = As[ak * 33 + row + 8];
            float a2 = As[(ak + 4) * 33 + row];
            float a3 = As[(ak + 4) * 33 + row + 8];
            unsigned ah[4], al[4];
            ah[0] = __float_as_uint(a0) & MASK;
            ah[1] = __float_as_uint(a1) & MASK;
            ah[2] = __float_as_uint(a2) & MASK;
            ah[3] = __float_as_uint(a3) & MASK;
            al[0] = __float_as_uint(a0 - __uint_as_float(ah[0]));
            al[1] = __float_as_uint(a1 - __uint_as_float(ah[1]));
            al[2] = __float_as_uint(a2 - __uint_as_float(ah[2]));
            al[3] = __float_as_uint(a3 - __uint_as_float(ah[3]));
            MMA_TF32(acc[mt], ah, bh);
            MMA_TF32(acc[mt], al, bh);
            MMA_TF32(acc[mt], ah, bl);
        }
    }
    // epilogue: partials (row = batch, col = j)
#pragma unroll
    for (int mt = 0; mt < 2; mt++) {
        int r = mt * 16 + (l >> 2);
        int c = colb + (l & 3) * 2;
        *(float2*)&g_synp[((size_t)kc * 32 + r) * 4096 + c] =
            make_float2(acc[mt][0], acc[mt][1]);
        *(float2*)&g_synp[((size_t)kc * 32 + r + 8) * 4096 + c] =
            make_float2(acc[mt][2], acc[mt][3]);
    }
}

// ----------------- loop phase 3: reduce + GLU + LN + trace -----------------
__global__ void __launch_bounds__(1024) k_phase3(const float* __restrict__ lng,
                                                 const float* __restrict__ lnb, int wslot) {
    int b = blockIdx.x, tid = threadIdx.x;
    __shared__ float red[32];
    float v[2];
    float s = 0.f;
#pragma unroll
    for (int q = 0; q < 2; q++) {
        int jj = tid + q * 1024;
        float a = g_synb2[jj], gg = g_synb2[jj + 2048];
#pragma unroll
        for (int c = 0; c < SYN_KC; c++) {
            a += g_synp[((size_t)c * 32 + b) * 4096 + jj];
            gg += g_synp[((size_t)c * 32 + b) * 4096 + jj + 2048];
        }
        v[q] = a * sigm(gg);
        s += v[q];
    }
    float mean = blockSumAll<32>(s, red) * (1.f / 2048.f);
    float s2 = 0.f;
#pragma unroll
    for (int q = 0; q < 2; q++) {
        float d = v[q] - mean;
        s2 += d * d;
    }
    float var = blockSumAll<32>(s2, red) * (1.f / 2048.f);
    float inv = rsqrtf(var + 1e-5f);
#pragma unroll
    for (int q = 0; q < 2; q++) {
        int jj = tid + q * 1024;
        float st = (v[q] - mean) * inv * lng[jj] + lnb[jj];
        g_trace[((size_t)b * 2048 + jj) * 25 + wslot] = st;
    }
}

// ----------------- loop phase 4: per-neuron NLM -----------------
__global__ void __launch_bounds__(256) k_nlm(const float* __restrict__ tp1b,
                                             const float* __restrict__ tp2b,
                                             int wslot, int p) {
    int d = blockIdx.x;
    __shared__ float w1s[3200];
    __shared__ float b1s[128];
    __shared__ float w2s[128];
    __shared__ float b2s[2];
    __shared__ float ts[32 * 25];
    __shared__ float red[8][32][2];
    int tid = threadIdx.x;
    {
        const float4* src = (const float4*)(g_tp1wt + (size_t)d * 3200);
        float4* dst = (float4*)w1s;
        for (int i = tid; i < 800; i += 256) dst[i] = src[i];
    }
    if (tid < 128) {
        b1s[tid] = tp1b[d * 128 + tid];
        w2s[tid] = g_tp2wt[d * 128 + tid];
    }
    if (tid < 2) b2s[tid] = tp2b[d * 2 + tid];
    for (int i = tid; i < 800; i += 256) {
        int b = i / 25, m = i % 25;
        int slot = wslot + 1 + m;
        if (slot >= 25) slot -= 25;
        ts[b * 25 + m] = g_trace[((size_t)b * 2048 + d) * 25 + slot];
    }
    __syncthreads();
    int lane = tid & 31;
    int wi = tid >> 5;
    int h0 = wi * 8;
    float a[8] = {}, gg[8] = {};
#pragma unroll
    for (int m = 0; m < 25; m++) {
        float tr = ts[lane * 25 + m];
        float4 a0 = *(const float4*)&w1s[m * 128 + h0];
        float4 a1 = *(const float4*)&w1s[m * 128 + h0 + 4];
        float4 g0 = *(const float4*)&w1s[m * 128 + h0 + 64];
        float4 g1 = *(const float4*)&w1s[m * 128 + h0 + 68];
        a[0] += tr * a0.x; a[1] += tr * a0.y; a[2] += tr * a0.z; a[3] += tr * a0.w;
        a[4] += tr * a1.x; a[5] += tr * a1.y; a[6] += tr * a1.z; a[7] += tr * a1.w;
        gg[0] += tr * g0.x; gg[1] += tr * g0.y; gg[2] += tr * g0.z; gg[3] += tr * g0.w;
        gg[4] += tr * g1.x; gg[5] += tr * g1.y; gg[6] += tr * g1.z; gg[7] += tr * g1.w;
    }
    float p0 = 0.f, p1 = 0.f;
#pragma unroll
    for (int j = 0; j < 8; j++) {
        float hv = (a[j] + b1s[h0 + j]) * sigm(gg[j] + b1s[h0 + 64 + j]);
        p0 += hv * w2s[(h0 + j) * 2];
        p1 += hv * w2s[(h0 + j) * 2 + 1];
    }
    red[wi][lane][0] = p0;
    red[wi][lane][1] = p1;
    __syncthreads();
    if (wi == 0) {
        float z0 = b2s[0], z1 = b2s[1];
#pragma unroll
        for (int k = 0; k < 8; k++) {
            z0 += red[k][lane][0];
            z1 += red[k][lane][1];
        }
        g_act[p][(size_t)lane * 2048 + d] = z0 * sigm(z1);
    }
}

// ----------------- out branch: syncO + out GEMM -----------------
__global__ void __launch_bounds__(256) k_outgemm(
    const float* __restrict__ out_w, const float* __restrict__ out_b,
    const int* __restrict__ il, const int* __restrict__ ir,
    float* __restrict__ dout, int t) {
    int b = blockIdx.y, oc = blockIdx.x;
    int tid = threadIdx.x;
    __shared__ float so[512];
    int p = t & 1;
    const float* act = g_act[p];
    for (int i = tid; i < 512; i += 256) {
        int n = i;
        float ro = g_ro[n];
        float prod = act[b * 2048 + il[n]] * act[b * 2048 + ir[n]];
        float dao = ro * g_dao[p][b * 512 + n] + prod;
        float dbo = ro * g_dbo[p][b * 512 + n] + 1.f;
        float sov = dao * rsqrtf(dbo);
        if (oc == 0) {
            g_dao[1 - p][b * 512 + n] = dao;
            g_dbo[1 - p][b * 512 + n] = dbo;
            if (t == 24) dout[800000 + 1600 + (size_t)b * 512 + n] = sov;
        }
        so[n] = sov;
    }
    __syncthreads();
    if (tid < 250) {
        int o = oc * 250 + tid;
        float acc = out_b[o];
#pragma unroll 4
        for (int n = 0; n < 512; n++) acc += so[n] * out_w[(size_t)n * 1000 + o];
        g_pred[b * 1000 + o] = acc;
        dout[(size_t)b * 25000 + (size_t)o * 25 + t] = acc;
    }
}

__global__ void k_entropy(float* __restrict__ dout, int t) {
    int b = blockIdx.x, tid = threadIdx.x;
    __shared__ float red[8];
    float mx = -3.4e38f;
    for (int o = tid; o < 1000; o += 256) mx = fmaxf(mx, g_pred[b * 1000 + o]);
    mx = blockMaxAll<8>(mx, red);
    float s = 0.f;
    for (int o = tid; o < 1000; o += 256) s += expf(g_pred[b * 1000 + o] - mx);
    s = blockSumAll<8>(s, red);
    float lse = mx + logf(s);
    float s2 = 0.f;
    for (int o = tid; o < 1000; o += 256) {
        float v = g_pred[b * 1000 + o] - lse;
        s2 += expf(v) * v;
    }
    s2 = blockSumAll<8>(s2, red);
    if (tid == 0) {
        float ne = -s2 / logf(1000.f);
        dout[800000 + (size_t)b * 50 + t] = ne;
        dout[800000 + (size_t)b * 50 + 25 + t] = 1.f - ne;
    }
}

// ----------------- host launcher -----------------
extern "C" void kernel_launch(void* const* d_in, const int* in_sizes, int n_in,
                              void* d_out, int out_size) {
    const float* x = (const float*)d_in[0];
    const float* kv_w = (const float*)d_in[1];
    const float* kv_b = (const float*)d_in[2];
    const float* kv_ln_g = (const float*)d_in[3];
    const float* kv_ln_b = (const float*)d_in[4];
    const float* q_w = (const float*)d_in[5];
    const float* q_b = (const float*)d_in[6];
    const float* attn_in_w = (const float*)d_in[7];
    const float* attn_in_b = (const float*)d_in[8];
    const float* attn_out_w = (const float*)d_in[9];
    const float* attn_out_b = (const float*)d_in[10];
    const float* syn_w = (const float*)d_in[11];
    const float* syn_b = (const float*)d_in[12];
    const float* syn_ln_g = (const float*)d_in[13];
    const float* syn_ln_b = (const float*)d_in[14];
    const float* tp1_w = (const float*)d_in[15];
    const float* tp1_b = (const float*)d_in[16];
    const float* tp2_w = (const float*)d_in[17];
    const float* tp2_b = (const float*)d_in[18];
    const float* sas = (const float*)d_in[19];
    const float* start_trace = (const float*)d_in[20];
    const float* decay_action = (const float*)d_in[21];
    const float* decay_out = (const float*)d_in[22];
    const float* out_w = (const float*)d_in[23];
    const float* out_b = (const float*)d_in[24];
    const int* idx_al = (const int*)d_in[25];
    const int* idx_ar = (const int*)d_in[26];
    const int* idx_ol = (const int*)d_in[27];
    const int* idx_or = (const int*)d_in[28];
    float* dout = (float*)d_out;

    float *p_kv, *p_KV, *p_Was;
    cudaGetSymbolAddress((void**)&p_kv, g_kv);
    cudaGetSymbolAddress((void**)&p_KV, g_KV);
    cudaGetSymbolAddress((void**)&p_Was, g_Was);

    static cudaStream_t s2 = nullptr;
    static cudaEvent_t evF = nullptr, evP = nullptr, evI = nullptr, evJ = nullptr;
    if (!s2) {
        cudaStreamCreateWithFlags(&s2, cudaStreamNonBlocking);
        cudaEventCreateWithFlags(&evF, cudaEventDisableTiming);
        cudaEventCreateWithFlags(&evP, cudaEventDisableTiming);
        cudaEventCreateWithFlags(&evI, cudaEventDisableTiming);
        cudaEventCreateWithFlags(&evJ, cudaEventDisableTiming);
    }

    // ---- preamble: fork tf32 Was-fold + misc onto s2; tf32 kv chain on main ----
    cudaEventRecord(evF, 0);
    cudaStreamWaitEvent(s2, evF, 0);
    k_tgemm<<<dim3(32, 8), 256, 0, s2>>>(attn_out_w, syn_w, (const float*)nullptr,
                                         p_Was, 512, 4096, 512, 4096, 1, 0);
    k_misc<<<7058, 256, 0, s2>>>(q_w, q_b, attn_in_w, attn_in_b, attn_out_b, syn_w, syn_b,
                                 tp1_w, tp2_w, sas, start_trace, idx_ol, idx_or,
                                 decay_action, decay_out);
    cudaEventRecord(evP, s2);

    k_tgemm<<<dim3(4, 128), 256>>>(x, kv_w, kv_b, p_kv, 8192, 512, 512, 512, 2, 0);
    k_ln512<<<8192, 256>>>(p_kv, kv_ln_g, kv_ln_b);
    k_tgemm<<<dim3(8, 128), 256>>>(p_kv, attn_in_w + 512 * 512, attn_in_b + 512,
                                   p_KV, 8192, 1024, 512, 1024, 0, 1);
    cudaStreamWaitEvent(0, evP, 0);

    // ---- 25 iterations: R6 loop structure (4 main nodes, forward fork to s2) ----
    for (int t = 0; t < NITER; t++) {
        int p = t & 1;
        k_phase1<<<256, 256>>>(idx_al, idx_ar, p);
        k_syngemm<<<dim3(64, SYN_KC), 256>>>(syn_w, p);
        k_phase3<<<32, 1024>>>(syn_ln_g, syn_ln_b, t);
        k_nlm<<<2048, 256>>>(tp1_b, tp2_b, t, p);
        cudaEventRecord(evI, 0);
        cudaStreamWaitEvent(s2, evI, 0);
        k_outgemm<<<dim3(4, 32), 256, 0, s2>>>(out_w, out_b, idx_ol, idx_or, dout, t);
        k_entropy<<<32, 256, 0, s2>>>(dout, t);
    }
    cudaEventRecord(evJ, s2);
    cudaStreamWaitEvent(0, evJ, 0);
}

// round 15
// speedup vs baseline: 1.1400x; 1.1400x over previous
#include <cuda_runtime.h>
#include <cuda_bf16.h>
#include <math.h>
#include <stdint.h>

#define NITER 25
#define SYN_KC 8

// ----------------- static device scratch -----------------
__device__ float g_kv[32 * 256 * 512];       // (b,s,d) post-LN
__device__ float g_KV[32 * 256 * 1024];      // (b,s,[K|V])
__device__ float g_WqqT[512 * 512];          // [e][n]
__device__ float g_bqq[512];
__device__ float g_Was[512 * 4096];          // aoT @ syn_w_top [d][j]
__device__ float g_synb2[4096];
__device__ float g_tp1wt[2048 * 3200];       // [d][m*128+h]
__device__ float g_tp2wt[2048 * 128];        // [d][h*2+o]
__device__ float g_act[2][32 * 2048];        // double-buffered
__device__ float g_trace[32 * 2048 * 25];    // ring on last dim
__device__ float g_daa[2][32 * 512];
__device__ float g_dba[2][32 * 512];
__device__ float g_dao[2][32 * 512];
__device__ float g_dbo[2][32 * 512];
__device__ float g_ra[512];
__device__ float g_ro[512];
__device__ float g_attn[32 * 512];
__device__ float g_synp[SYN_KC * 32 * 4096]; // split-K partials
__device__ float g_pred[32 * 1000];

// ----------------- helpers -----------------
__device__ __forceinline__ float warpSum(float v) {
#pragma unroll
    for (int o = 16; o; o >>= 1) v += __shfl_down_sync(0xffffffffu, v, o);
    return v;
}
__device__ __forceinline__ float warpMax(float v) {
#pragma unroll
    for (int o = 16; o; o >>= 1) v = fmaxf(v, __shfl_down_sync(0xffffffffu, v, o));
    return v;
}
template<int NW>
__device__ __forceinline__ float blockSumAll(float v, volatile float* red) {
    float s = warpSum(v);
    __syncthreads();
    if ((threadIdx.x & 31) == 0) red[threadIdx.x >> 5] = s;
    __syncthreads();
    float t = 0.f;
#pragma unroll
    for (int i = 0; i < NW; i++) t += red[i];
    return t;
}
template<int NW>
__device__ __forceinline__ float blockMaxAll(float v, volatile float* red) {
    float s = warpMax(v);
    __syncthreads();
    if ((threadIdx.x & 31) == 0) red[threadIdx.x >> 5] = s;
    __syncthreads();
    float t = -3.4e38f;
#pragma unroll
    for (int i = 0; i < NW; i++) t = fmaxf(t, red[i]);
    return t;
}
__device__ __forceinline__ float sigm(float x) { return 1.f / (1.f + expf(-x)); }

#define MMA_TF32(c, a, b)                                               \
    asm volatile(                                                       \
        "mma.sync.aligned.m16n8k8.row.col.f32.tf32.tf32.f32 "           \
        "{%0,%1,%2,%3}, {%4,%5,%6,%7}, {%8,%9}, {%0,%1,%2,%3};"         \
        : "+f"((c)[0]), "+f"((c)[1]), "+f"((c)[2]), "+f"((c)[3])        \
        : "r"((a)[0]), "r"((a)[1]), "r"((a)[2]), "r"((a)[3]),           \
          "r"((b)[0]), "r"((b)[1]))

// ----------------- 3xTF32 big GEMM (preamble): 64m x 128n tile -----------------
// amode 0: A row-major. amode 1: A col-major (lda=M). amode 2: x tensor.
__global__ void __launch_bounds__(256) k_tgemm(
    const float* __restrict__ A, const float* __restrict__ Bm,
    const float* __restrict__ bias, float* __restrict__ Cm,
    int M, int N, int K, int ldc, int amode, int transB) {
    __shared__ float As[32][68];
    __shared__ float Bs[32][132];
    int m0 = blockIdx.y * 64, n0 = blockIdx.x * 128;
    int tid = threadIdx.x;
    int w = tid >> 5, l = tid & 31;
    int wm = w >> 2, wn = w & 3;
    const unsigned MASK = 0xffffe000u;
    float acc[2][4][4] = {};
    for (int k0 = 0; k0 < K; k0 += 32) {
        if (amode == 0) {
#pragma unroll
            for (int r = 0; r < 2; r++) {
                int idx = tid + r * 256;
                int m = idx >> 3;
                int k4 = (idx & 7) * 4;
                float4 v = *(const float4*)&A[(size_t)(m0 + m) * K + k0 + k4];
                As[k4 + 0][m] = v.x; As[k4 + 1][m] = v.y;
                As[k4 + 2][m] = v.z; As[k4 + 3][m] = v.w;
            }
        } else if (amode == 1) {
#pragma unroll
            for (int r = 0; r < 2; r++) {
                int idx = tid + r * 256;
                int k = idx >> 4;
                int m4 = (idx & 15) * 4;
                float4 v = *(const float4*)&A[(size_t)(k0 + k) * M + m0 + m4];
                *(float4*)&As[k][m4] = v;
            }
        } else {
            int b0 = m0 >> 8, s0 = m0 & 255;
#pragma unroll
            for (int r = 0; r < 2; r++) {
                int idx = tid + r * 256;
                int k = idx >> 4;
                int m4 = (idx & 15) * 4;
                float4 v = *(const float4*)&A[(size_t)b0 * 131072 + (size_t)(k0 + k) * 256 + s0 + m4];
                *(float4*)&As[k][m4] = v;
            }
        }
        if (!transB) {
#pragma unroll
            for (int r = 0; r < 4; r++) {
                int idx = tid + r * 256;
                int k = idx >> 5;
                int n4 = (idx & 31) * 4;
                float4 v = *(const float4*)&Bm[(size_t)(k0 + k) * N + n0 + n4];
                *(float4*)&Bs[k][n4] = v;
            }
        } else {
#pragma unroll
            for (int r = 0; r < 4; r++) {
                int idx = tid + r * 256;
                int n = idx >> 3;
                int k4 = (idx & 7) * 4;
                float4 v = *(const float4*)&Bm[(size_t)(n0 + n) * K + k0 + k4];
                Bs[k4 + 0][n] = v.x; Bs[k4 + 1][n] = v.y;
                Bs[k4 + 2][n] = v.z; Bs[k4 + 3][n] = v.w;
            }
        }
        __syncthreads();
#pragma unroll
        for (int ks = 0; ks < 4; ks++) {
            int kb = ks * 8;
            unsigned bh[4][2], bl[4][2];
#pragma unroll
            for (int nt = 0; nt < 4; nt++) {
                int col = wn * 32 + nt * 8 + (l >> 2);
                float b0 = Bs[kb + (l & 3)][col];
                float b1 = Bs[kb + (l & 3) + 4][col];
                unsigned u0 = __float_as_uint(b0) & MASK;
                unsigned u1 = __float_as_uint(b1) & MASK;
                bh[nt][0] = u0;
                bh[nt][1] = u1;
                bl[nt][0] = __float_as_uint(b0 - __uint_as_float(u0));
                bl[nt][1] = __float_as_uint(b1 - __uint_as_float(u1));
            }
#pragma unroll
            for (int mt = 0; mt < 2; mt++) {
                int row = wm * 32 + mt * 16 + (l >> 2);
                int ak = kb + (l & 3);
                float a0 = As[ak][row];
                float a1 = As[ak][row + 8];
                float a2 = As[ak + 4][row];
                float a3 = As[ak + 4][row + 8];
                unsigned ah[4], al[4];
                ah[0] = __float_as_uint(a0) & MASK;
                ah[1] = __float_as_uint(a1) & MASK;
                ah[2] = __float_as_uint(a2) & MASK;
                ah[3] = __float_as_uint(a3) & MASK;
                al[0] = __float_as_uint(a0 - __uint_as_float(ah[0]));
                al[1] = __float_as_uint(a1 - __uint_as_float(ah[1]));
                al[2] = __float_as_uint(a2 - __uint_as_float(ah[2]));
                al[3] = __float_as_uint(a3 - __uint_as_float(ah[3]));
#pragma unroll
                for (int nt = 0; nt < 4; nt++) {
                    MMA_TF32(acc[mt][nt], ah, bh[nt]);
                    MMA_TF32(acc[mt][nt], al, bh[nt]);
                    MMA_TF32(acc[mt][nt], ah, bl[nt]);
                }
            }
        }
        __syncthreads();
    }
#pragma unroll
    for (int mt = 0; mt < 2; mt++)
#pragma unroll
        for (int nt = 0; nt < 4; nt++) {
            int r = m0 + wm * 32 + mt * 16 + (l >> 2);
            int c = n0 + wn * 32 + nt * 8 + (l & 3) * 2;
            float b0 = bias ? bias[c] : 0.f;
            float b1 = bias ? bias[c + 1] : 0.f;
            *(float2*)&Cm[(size_t)r * ldc + c] =
                make_float2(acc[mt][nt][0] + b0, acc[mt][nt][1] + b1);
            *(float2*)&Cm[(size_t)(r + 8) * ldc + c] =
                make_float2(acc[mt][nt][2] + b0, acc[mt][nt][3] + b1);
        }
}

// ----------------- LN over rows of 512 (preamble) -----------------
__global__ void k_ln512(float* __restrict__ buf, const float* __restrict__ g,
                        const float* __restrict__ bb) {
    __shared__ float red[8];
    float* p = buf + (size_t)blockIdx.x * 512;
    int tid = threadIdx.x;
    float v0 = p[tid], v1 = p[tid + 256];
    float mean = blockSumAll<8>(v0 + v1, red) * (1.f / 512.f);
    float d0 = v0 - mean, d1 = v1 - mean;
    float var = blockSumAll<8>(d0 * d0 + d1 * d1, red) * (1.f / 512.f);
    float inv = rsqrtf(var + 1e-5f);
    p[tid] = d0 * inv * g[tid] + bb[tid];
    p[tid + 256] = d1 * inv * g[tid + 256] + bb[tid + 256];
}

// ----------------- misc init mega-kernel (preamble) -----------------
__device__ __forceinline__ void transpose_tile(const float* __restrict__ in,
                                               float* __restrict__ out,
                                               int R, int Cc, int tr, int tc) {
    __shared__ float t[32][33];
    int tid = threadIdx.x;
    int lx = tid & 31, ly = tid >> 5;
    int r0 = tr * 32, c0 = tc * 32;
#pragma unroll
    for (int i = ly; i < 32; i += 8)
        t[i][lx] = in[(size_t)(r0 + i) * Cc + c0 + lx];
    __syncthreads();
#pragma unroll
    for (int i = ly; i < 32; i += 8)
        out[(size_t)(c0 + i) * R + r0 + lx] = t[lx][i];
}

__global__ void __launch_bounds__(256) k_misc(
    const float* __restrict__ q_w, const float* __restrict__ q_b,
    const float* __restrict__ attn_in_w, const float* __restrict__ attn_in_b,
    const float* __restrict__ attn_out_b,
    const float* __restrict__ syn_w, const float* __restrict__ syn_b,
    const float* __restrict__ tp1_w, const float* __restrict__ tp2_w,
    const float* __restrict__ sas, const float* __restrict__ st,
    const int* __restrict__ ol, const int* __restrict__ orr,
    const float* __restrict__ da, const float* __restrict__ dco) {
    int blk = blockIdx.x;
    int tid = threadIdx.x;
    if (blk < 64) {
        __shared__ float As[16][65];
        __shared__ float Bs[16][65];
        int m0 = (blk >> 3) * 64, n0 = (blk & 7) * 64;
        int tx = tid % 16, ty = tid / 16;
        float acc[4][4] = {};
        for (int k0 = 0; k0 < 512; k0 += 16) {
#pragma unroll
            for (int p = 0; p < 4; p++) {
                int m = ty + p * 16;
                As[tx][m] = attn_in_w[(size_t)(m0 + m) * 512 + k0 + tx];
                Bs[tx][m] = q_w[(size_t)(n0 + m) * 512 + k0 + tx];
            }
            __syncthreads();
#pragma unroll
            for (int k = 0; k < 16; k++) {
                float a[4], b[4];
#pragma unroll
                for (int i = 0; i < 4; i++) a[i] = As[k][ty * 4 + i];
#pragma unroll
                for (int j = 0; j < 4; j++) b[j] = Bs[k][tx * 4 + j];
#pragma unroll
                for (int i = 0; i < 4; i++)
#pragma unroll
                    for (int j = 0; j < 4; j++) acc[i][j] += a[i] * b[j];
            }
            __syncthreads();
        }
#pragma unroll
        for (int i = 0; i < 4; i++)
#pragma unroll
            for (int j = 0; j < 4; j++)
                g_WqqT[(size_t)(m0 + ty * 4 + i) * 512 + n0 + tx * 4 + j] = acc[i][j];
    } else if (blk < 6464) {
        int tIdx = blk - 64;
        transpose_tile(tp1_w, g_tp1wt, 3200, 2048, tIdx / 64, tIdx % 64);
    } else if (blk < 6720) {
        int tIdx = blk - 6464;
        transpose_tile(tp2_w, g_tp2wt, 128, 2048, tIdx / 64, tIdx % 64);
    } else if (blk < 6722) {
        int e = (blk - 6720) * 256 + tid;
        float s = attn_in_b[e];
        for (int d = 0; d < 512; d++) s += q_b[d] * attn_in_w[(size_t)e * 512 + d];
        g_bqq[e] = s;
    } else if (blk < 6738) {
        int j = (blk - 6722) * 256 + tid;
        float s = syn_b[j];
        for (int e = 0; e < 512; e++) s += attn_out_b[e] * syn_w[(size_t)e * 4096 + j];
        g_synb2[j] = s;
    } else if (blk < 6994) {
        int i = (blk - 6738) * 256 + tid;
        int d = i & 2047;
        g_act[1][i] = sas[d];
#pragma unroll
        for (int s = 0; s < 25; s++) g_trace[(size_t)i * 25 + s] = st[d * 25 + s];
    } else {
        int i = (blk - 6994) * 256 + tid;
        int n = i & 511;
        g_daa[0][i] = 0.f;
        g_dba[0][i] = 0.f;
        g_dao[0][i] = sas[ol[n]] * sas[orr[n]];
        g_dbo[0][i] = 1.f;
        if (i < 512) {
            g_ra[i] = expf(-fminf(fmaxf(da[i], 0.f), 15.f));
            g_ro[i] = expf(-fminf(fmaxf(dco[i], 0.f), 15.f));
        }
    }
}

// ----------------- loop phase 1: syncA + q + attention -----------------
__global__ void __launch_bounds__(256) k_phase1(const int* __restrict__ il,
                                                const int* __restrict__ ir, int p) {
    int b = blockIdx.x >> 3, h = blockIdx.x & 7;
    __shared__ float sa[512];
    __shared__ float qh[64];
    __shared__ float pr[256];
    __shared__ float red[8];
    __shared__ float av[4][64];
    int tid = threadIdx.x;
    const float* act = g_act[1 - p];
#pragma unroll
    for (int r = 0; r < 2; r++) {
        int n = tid + r * 256;
        float ra = g_ra[n];
        float prod = act[b * 2048 + il[n]] * act[b * 2048 + ir[n]];
        float daa = ra * g_daa[p][b * 512 + n] + prod;
        float dba = ra * g_dba[p][b * 512 + n] + 1.f;
        if (h == 0) {
            g_daa[1 - p][b * 512 + n] = daa;
            g_dba[1 - p][b * 512 + n] = dba;
        }
        sa[n] = daa * rsqrtf(dba);
    }
    __syncthreads();
    {
        int e = tid >> 2, qd = tid & 3;
        const float* wr = g_WqqT + (size_t)(h * 64 + e) * 512 + qd * 128;
        const float* sap = sa + qd * 128;
        float acc = 0.f;
#pragma unroll
        for (int k = 0; k < 128; k += 4) {
            float4 w = *(const float4*)&wr[k];
            acc += sap[k] * w.x + sap[k + 1] * w.y + sap[k + 2] * w.z + sap[k + 3] * w.w;
        }
        acc += __shfl_down_sync(0xffffffffu, acc, 2);
        acc += __shfl_down_sync(0xffffffffu, acc, 1);
        if (qd == 0) qh[e] = acc + g_bqq[h * 64 + e];
    }
    __syncthreads();
    const float* Kp = g_KV + ((size_t)(b * 256 + tid)) * 1024 + h * 64;
    float sc = 0.f;
#pragma unroll
    for (int d4 = 0; d4 < 64; d4 += 4) {
        float4 kvv = *(const float4*)&Kp[d4];
        sc += qh[d4] * kvv.x + qh[d4 + 1] * kvv.y + qh[d4 + 2] * kvv.z + qh[d4 + 3] * kvv.w;
    }
    sc *= 0.125f;
    float mall = blockMaxAll<8>(sc, red);
    float e1 = expf(sc - mall);
    float ssum = blockSumAll<8>(e1, red);
    pr[tid] = e1 / ssum;
    __syncthreads();
    int dd = tid & 63, qq = tid >> 6;
    const float* Vp = g_KV + ((size_t)(b * 256 + qq * 64)) * 1024 + 512 + h * 64 + dd;
    float acc = 0.f;
#pragma unroll 8
    for (int j = 0; j < 64; j++) acc += pr[qq * 64 + j] * Vp[(size_t)j * 1024];
    av[qq][dd] = acc;
    __syncthreads();
    if (tid < 64)
        g_attn[b * 512 + h * 64 + tid] = av[0][tid] + av[1][tid] + av[2][tid] + av[3][tid];
}

// ----------------- loop phase 2: fp32 syn GEMM, split-K x8 (k-chunk 320) -----------------
__global__ void __launch_bounds__(256) k_syngemm(const float* __restrict__ syn_w, int p) {
    __shared__ float As[32 * 32];
    int tid = threadIdx.x;
    int nt = tid & 31, bt = tid >> 5;
    int n0 = blockIdx.x * 128;
    int kc = blockIdx.y;
    const float* act = g_act[1 - p];
    float acc[4][4] = {};
    for (int ks = 0; ks < 320; ks += 32) {
        int k0 = kc * 320 + ks;
        __syncthreads();
#pragma unroll
        for (int r = 0; r < 4; r++) {
            int idx = tid + r * 256;
            int kk = idx >> 5, b = idx & 31;
            int k = k0 + kk;
            As[kk * 32 + b] = (k < 512) ? g_attn[b * 512 + k] : act[b * 2048 + (k - 512)];
        }
        __syncthreads();
        const float* Wp = (k0 < 512) ? (g_Was + (size_t)k0 * 4096 + n0)
                                     : (syn_w + (size_t)k0 * 4096 + n0);
#pragma unroll 8
        for (int kk = 0; kk < 32; kk++) {
            float4 a = *(const float4*)&As[kk * 32 + bt * 4];
            float4 w = *(const float4*)&Wp[(size_t)kk * 4096 + nt * 4];
            float avv[4] = {a.x, a.y, a.z, a.w};
            float wv[4] = {w.x, w.y, w.z, w.w};
#pragma unroll
            for (int bi = 0; bi < 4; bi++)
#pragma unroll
                for (int nj = 0; nj < 4; nj++) acc[bi][nj] += avv[bi] * wv[nj];
        }
    }
#pragma unroll
    for (int bi = 0; bi < 4; bi++) {
        int b = bt * 4 + bi;
        float* dst = g_synp + ((size_t)kc * 32 + b) * 4096 + n0;
        *(float4*)&dst[nt * 4] = *(float4*)&acc[bi][0];
    }
}

// ----------------- loop phase 3: reduce + GLU + LN + trace -----------------
__global__ void __launch_bounds__(1024) k_phase3(const float* __restrict__ lng,
                                                 const float* __restrict__ lnb, int wslot) {
    int b = blockIdx.x, tid = threadIdx.x;
    __shared__ float red[32];
    float v[2];
    float s = 0.f;
#pragma unroll
    for (int q = 0; q < 2; q++) {
        int jj = tid + q * 1024;
        float a = g_synb2[jj], gg = g_synb2[jj + 2048];
#pragma unroll
        for (int c = 0; c < SYN_KC; c++) {
            a += g_synp[((size_t)c * 32 + b) * 4096 + jj];
            gg += g_synp[((size_t)c * 32 + b) * 4096 + jj + 2048];
        }
        v[q] = a * sigm(gg);
        s += v[q];
    }
    float mean = blockSumAll<32>(s, red) * (1.f / 2048.f);
    float s2 = 0.f;
#pragma unroll
    for (int q = 0; q < 2; q++) {
        float d = v[q] - mean;
        s2 += d * d;
    }
    float var = blockSumAll<32>(s2, red) * (1.f / 2048.f);
    float inv = rsqrtf(var + 1e-5f);
#pragma unroll
    for (int q = 0; q < 2; q++) {
        int jj = tid + q * 1024;
        float st = (v[q] - mean) * inv * lng[jj] + lnb[jj];
        g_trace[((size_t)b * 2048 + jj) * 25 + wslot] = st;
    }
}

// ----------------- loop phase 4: per-neuron NLM -----------------
__global__ void __launch_bounds__(256) k_nlm(const float* __restrict__ tp1b,
                                             const float* __restrict__ tp2b,
                                             int wslot, int p) {
    int d = blockIdx.x;
    __shared__ float w1s[3200];
    __shared__ float b1s[128];
    __shared__ float w2s[128];
    __shared__ float b2s[2];
    __shared__ float ts[32 * 25];
    __shared__ float red[8][32][2];
    int tid = threadIdx.x;
    {
        const float4* src = (const float4*)(g_tp1wt + (size_t)d * 3200);
        float4* dst = (float4*)w1s;
        for (int i = tid; i < 800; i += 256) dst[i] = src[i];
    }
    if (tid < 128) {
        b1s[tid] = tp1b[d * 128 + tid];
        w2s[tid] = g_tp2wt[d * 128 + tid];
    }
    if (tid < 2) b2s[tid] = tp2b[d * 2 + tid];
    for (int i = tid; i < 800; i += 256) {
        int b = i / 25, m = i % 25;
        int slot = wslot + 1 + m;
        if (slot >= 25) slot -= 25;
        ts[b * 25 + m] = g_trace[((size_t)b * 2048 + d) * 25 + slot];
    }
    __syncthreads();
    int lane = tid & 31;
    int wi = tid >> 5;
    int h0 = wi * 8;
    float a[8] = {}, gg[8] = {};
#pragma unroll
    for (int m = 0; m < 25; m++) {
        float tr = ts[lane * 25 + m];
        float4 a0 = *(const float4*)&w1s[m * 128 + h0];
        float4 a1 = *(const float4*)&w1s[m * 128 + h0 + 4];
        float4 g0 = *(const float4*)&w1s[m * 128 + h0 + 64];
        float4 g1 = *(const float4*)&w1s[m * 128 + h0 + 68];
        a[0] += tr * a0.x; a[1] += tr * a0.y; a[2] += tr * a0.z; a[3] += tr * a0.w;
        a[4] += tr * a1.x; a[5] += tr * a1.y; a[6] += tr * a1.z; a[7] += tr * a1.w;
        gg[0] += tr * g0.x; gg[1] += tr * g0.y; gg[2] += tr * g0.z; gg[3] += tr * g0.w;
        gg[4] += tr * g1.x; gg[5] += tr * g1.y; gg[6] += tr * g1.z; gg[7] += tr * g1.w;
    }
    float p0 = 0.f, p1 = 0.f;
#pragma unroll
    for (int j = 0; j < 8; j++) {
        float hv = (a[j] + b1s[h0 + j]) * sigm(gg[j] + b1s[h0 + 64 + j]);
        p0 += hv * w2s[(h0 + j) * 2];
        p1 += hv * w2s[(h0 + j) * 2 + 1];
    }
    red[wi][lane][0] = p0;
    red[wi][lane][1] = p1;
    __syncthreads();
    if (wi == 0) {
        float z0 = b2s[0], z1 = b2s[1];
#pragma unroll
        for (int k = 0; k < 8; k++) {
            z0 += red[k][lane][0];
            z1 += red[k][lane][1];
        }
        g_act[p][(size_t)lane * 2048 + d] = z0 * sigm(z1);
    }
}

// ----------------- out branch: syncO + out GEMM -----------------
__global__ void __launch_bounds__(256) k_outgemm(
    const float* __restrict__ out_w, const float* __restrict__ out_b,
    const int* __restrict__ il, const int* __restrict__ ir,
    float* __restrict__ dout, int t) {
    int b = blockIdx.y, oc = blockIdx.x;
    int tid = threadIdx.x;
    __shared__ float so[512];
    int p = t & 1;
    const float* act = g_act[p];
    for (int i = tid; i < 512; i += 256) {
        int n = i;
        float ro = g_ro[n];
        float prod = act[b * 2048 + il[n]] * act[b * 2048 + ir[n]];
        float dao = ro * g_dao[p][b * 512 + n] + prod;
        float dbo = ro * g_dbo[p][b * 512 + n] + 1.f;
        float sov = dao * rsqrtf(dbo);
        if (oc == 0) {
            g_dao[1 - p][b * 512 + n] = dao;
            g_dbo[1 - p][b * 512 + n] = dbo;
            if (t == 24) dout[800000 + 1600 + (size_t)b * 512 + n] = sov;
        }
        so[n] = sov;
    }
    __syncthreads();
    if (tid < 250) {
        int o = oc * 250 + tid;
        float acc = out_b[o];
#pragma unroll 4
        for (int n = 0; n < 512; n++) acc += so[n] * out_w[(size_t)n * 1000 + o];
        g_pred[b * 1000 + o] = acc;
        dout[(size_t)b * 25000 + (size_t)o * 25 + t] = acc;
    }
}

__global__ void k_entropy(float* __restrict__ dout, int t) {
    int b = blockIdx.x, tid = threadIdx.x;
    __shared__ float red[8];
    float mx = -3.4e38f;
    for (int o = tid; o < 1000; o += 256) mx = fmaxf(mx, g_pred[b * 1000 + o]);
    mx = blockMaxAll<8>(mx, red);
    float s = 0.f;
    for (int o = tid; o < 1000; o += 256) s += expf(g_pred[b * 1000 + o] - mx);
    s = blockSumAll<8>(s, red);
    float lse = mx + logf(s);
    float s2 = 0.f;
    for (int o = tid; o < 1000; o += 256) {
        float v = g_pred[b * 1000 + o] - lse;
        s2 += expf(v) * v;
    }
    s2 = blockSumAll<8>(s2, red);
    if (tid == 0) {
        float ne = -s2 / logf(1000.f);
        dout[800000 + (size_t)b * 50 + t] = ne;
        dout[800000 + (size_t)b * 50 + 25 + t] = 1.f - ne;
    }
}

// ----------------- host launcher -----------------
extern "C" void kernel_launch(void* const* d_in, const int* in_sizes, int n_in,
                              void* d_out, int out_size) {
    const float* x = (const float*)d_in[0];
    const float* kv_w = (const float*)d_in[1];
    const float* kv_b = (const float*)d_in[2];
    const float* kv_ln_g = (const float*)d_in[3];
    const float* kv_ln_b = (const float*)d_in[4];
    const float* q_w = (const float*)d_in[5];
    const float* q_b = (const float*)d_in[6];
    const float* attn_in_w = (const float*)d_in[7];
    const float* attn_in_b = (const float*)d_in[8];
    const float* attn_out_w = (const float*)d_in[9];
    const float* attn_out_b = (const float*)d_in[10];
    const float* syn_w = (const float*)d_in[11];
    const float* syn_b = (const float*)d_in[12];
    const float* syn_ln_g = (const float*)d_in[13];
    const float* syn_ln_b = (const float*)d_in[14];
    const float* tp1_w = (const float*)d_in[15];
    const float* tp1_b = (const float*)d_in[16];
    const float* tp2_w = (const float*)d_in[17];
    const float* tp2_b = (const float*)d_in[18];
    const float* sas = (const float*)d_in[19];
    const float* start_trace = (const float*)d_in[20];
    const float* decay_action = (const float*)d_in[21];
    const float* decay_out = (const float*)d_in[22];
    const float* out_w = (const float*)d_in[23];
    const float* out_b = (const float*)d_in[24];
    const int* idx_al = (const int*)d_in[25];
    const int* idx_ar = (const int*)d_in[26];
    const int* idx_ol = (const int*)d_in[27];
    const int* idx_or = (const int*)d_in[28];
    float* dout = (float*)d_out;

    float *p_kv, *p_KV, *p_Was;
    cudaGetSymbolAddress((void**)&p_kv, g_kv);
    cudaGetSymbolAddress((void**)&p_KV, g_KV);
    cudaGetSymbolAddress((void**)&p_Was, g_Was);

    static cudaStream_t s2 = nullptr;
    static cudaEvent_t evF = nullptr, evP = nullptr, evI = nullptr, evJ = nullptr;
    if (!s2) {
        cudaStreamCreateWithFlags(&s2, cudaStreamNonBlocking);
        cudaEventCreateWithFlags(&evF, cudaEventDisableTiming);
        cudaEventCreateWithFlags(&evP, cudaEventDisableTiming);
        cudaEventCreateWithFlags(&evI, cudaEventDisableTiming);
        cudaEventCreateWithFlags(&evJ, cudaEventDisableTiming);
    }

    // ---- preamble: fork tf32 Was-fold + misc onto s2; tf32 kv chain on main ----
    cudaEventRecord(evF, 0);
    cudaStreamWaitEvent(s2, evF, 0);
    k_tgemm<<<dim3(32, 8), 256, 0, s2>>>(attn_out_w, syn_w, (const float*)nullptr,
                                         p_Was, 512, 4096, 512, 4096, 1, 0);
    k_misc<<<7058, 256, 0, s2>>>(q_w, q_b, attn_in_w, attn_in_b, attn_out_b, syn_w, syn_b,
                                 tp1_w, tp2_w, sas, start_trace, idx_ol, idx_or,
                                 decay_action, decay_out);
    cudaEventRecord(evP, s2);

    k_tgemm<<<dim3(4, 128), 256>>>(x, kv_w, kv_b, p_kv, 8192, 512, 512, 512, 2, 0);
    k_ln512<<<8192, 256>>>(p_kv, kv_ln_g, kv_ln_b);
    k_tgemm<<<dim3(8, 128), 256>>>(p_kv, attn_in_w + 512 * 512, attn_in_b + 512,
                                   p_KV, 8192, 1024, 512, 1024, 0, 1);
    cudaStreamWaitEvent(0, evP, 0);

    // ---- 25 iterations: R13 loop structure (4 main nodes, forward fork to s2) ----
    for (int t = 0; t < NITER; t++) {
        int p = t & 1;
        k_phase1<<<256, 256>>>(idx_al, idx_ar, p);
        k_syngemm<<<dim3(32, SYN_KC), 256>>>(syn_w, p);
        k_phase3<<<32, 1024>>>(syn_ln_g, syn_ln_b, t);
        k_nlm<<<2048, 256>>>(tp1_b, tp2_b, t, p);
        cudaEventRecord(evI, 0);
        cudaStreamWaitEvent(s2, evI, 0);
        k_outgemm<<<dim3(4, 32), 256, 0, s2>>>(out_w, out_b, idx_ol, idx_or, dout, t);
        k_entropy<<<32, 256, 0, s2>>>(dout, t);
    }
    cudaEventRecord(evJ, s2);
    cudaStreamWaitEvent(0, evJ, 0);
}

// round 16
// speedup vs baseline: 1.3724x; 1.2039x over previous
#include <cuda_runtime.h>
#include <cuda_bf16.h>
#include <math.h>
#include <stdint.h>

#define NITER 25
#define SYN_KC 16

#define FMA2(c, a, b) \
    asm("fma.rn.f32x2 %0, %1, %2, %0;" : "+l"(c) : "l"(a), "l"(b))
#define PACK2(d, f) \
    asm("mov.b64 %0, {%1,%1};" : "=l"(d) : "f"(f))
#define UNPACK2(lo, hi, v) \
    asm("mov.b64 {%0,%1}, %2;" : "=f"(lo), "=f"(hi) : "l"(v))

// ----------------- static device scratch -----------------
__device__ float g_kv[32 * 256 * 512];
__device__ float g_KV[32 * 256 * 1024];
__device__ float g_WqqT[512 * 512];
__device__ float g_bqq[512];
__device__ float g_Was[512 * 4096];
__device__ float g_synb2[4096];
__device__ float g_tp1wt[2048 * 3200];
__device__ float g_tp2wt[2048 * 128];
__device__ float g_act[2][32 * 2048];
__device__ float g_trace[32 * 2048 * 25];
__device__ float g_daa[2][32 * 512];
__device__ float g_dba[2][32 * 512];
__device__ float g_dao[2][32 * 512];
__device__ float g_dbo[2][32 * 512];
__device__ float g_ra[512];
__device__ float g_ro[512];
__device__ float g_attn[32 * 512];
__device__ float g_synp[SYN_KC * 32 * 4096];
__device__ float g_pred[32 * 1000];

// ----------------- helpers -----------------
__device__ __forceinline__ float warpSum(float v) {
#pragma unroll
    for (int o = 16; o; o >>= 1) v += __shfl_down_sync(0xffffffffu, v, o);
    return v;
}
__device__ __forceinline__ float warpMax(float v) {
#pragma unroll
    for (int o = 16; o; o >>= 1) v = fmaxf(v, __shfl_down_sync(0xffffffffu, v, o));
    return v;
}
template<int NW>
__device__ __forceinline__ float blockSumAll(float v, volatile float* red) {
    float s = warpSum(v);
    __syncthreads();
    if ((threadIdx.x & 31) == 0) red[threadIdx.x >> 5] = s;
    __syncthreads();
    float t = 0.f;
#pragma unroll
    for (int i = 0; i < NW; i++) t += red[i];
    return t;
}
template<int NW>
__device__ __forceinline__ float blockMaxAll(float v, volatile float* red) {
    float s = warpMax(v);
    __syncthreads();
    if ((threadIdx.x & 31) == 0) red[threadIdx.x >> 5] = s;
    __syncthreads();
    float t = -3.4e38f;
#pragma unroll
    for (int i = 0; i < NW; i++) t = fmaxf(t, red[i]);
    return t;
}
__device__ __forceinline__ float sigm(float x) { return 1.f / (1.f + expf(-x)); }

#define MMA_TF32(c, a, b)                                               \
    asm volatile(                                                       \
        "mma.sync.aligned.m16n8k8.row.col.f32.tf32.tf32.f32 "           \
        "{%0,%1,%2,%3}, {%4,%5,%6,%7}, {%8,%9}, {%0,%1,%2,%3};"         \
        : "+f"((c)[0]), "+f"((c)[1]), "+f"((c)[2]), "+f"((c)[3])        \
        : "r"((a)[0]), "r"((a)[1]), "r"((a)[2]), "r"((a)[3]),           \
          "r"((b)[0]), "r"((b)[1]))

// ----------------- 3xTF32 big GEMM (preamble): 64m x 128n tile -----------------
__global__ void __launch_bounds__(256) k_tgemm(
    const float* __restrict__ A, const float* __restrict__ Bm,
    const float* __restrict__ bias, float* __restrict__ Cm,
    int M, int N, int K, int ldc, int amode, int transB) {
    __shared__ float As[32][68];
    __shared__ float Bs[32][132];
    int m0 = blockIdx.y * 64, n0 = blockIdx.x * 128;
    int tid = threadIdx.x;
    int w = tid >> 5, l = tid & 31;
    int wm = w >> 2, wn = w & 3;
    const unsigned MASK = 0xffffe000u;
    float acc[2][4][4] = {};
    for (int k0 = 0; k0 < K; k0 += 32) {
        if (amode == 0) {
#pragma unroll
            for (int r = 0; r < 2; r++) {
                int idx = tid + r * 256;
                int m = idx >> 3;
                int k4 = (idx & 7) * 4;
                float4 v = *(const float4*)&A[(size_t)(m0 + m) * K + k0 + k4];
                As[k4 + 0][m] = v.x; As[k4 + 1][m] = v.y;
                As[k4 + 2][m] = v.z; As[k4 + 3][m] = v.w;
            }
        } else if (amode == 1) {
#pragma unroll
            for (int r = 0; r < 2; r++) {
                int idx = tid + r * 256;
                int k = idx >> 4;
                int m4 = (idx & 15) * 4;
                float4 v = *(const float4*)&A[(size_t)(k0 + k) * M + m0 + m4];
                *(float4*)&As[k][m4] = v;
            }
        } else {
            int b0 = m0 >> 8, s0 = m0 & 255;
#pragma unroll
            for (int r = 0; r < 2; r++) {
                int idx = tid + r * 256;
                int k = idx >> 4;
                int m4 = (idx & 15) * 4;
                float4 v = *(const float4*)&A[(size_t)b0 * 131072 + (size_t)(k0 + k) * 256 + s0 + m4];
                *(float4*)&As[k][m4] = v;
            }
        }
        if (!transB) {
#pragma unroll
            for (int r = 0; r < 4; r++) {
                int idx = tid + r * 256;
                int k = idx >> 5;
                int n4 = (idx & 31) * 4;
                float4 v = *(const float4*)&Bm[(size_t)(k0 + k) * N + n0 + n4];
                *(float4*)&Bs[k][n4] = v;
            }
        } else {
#pragma unroll
            for (int r = 0; r < 4; r++) {
                int idx = tid + r * 256;
                int n = idx >> 3;
                int k4 = (idx & 7) * 4;
                float4 v = *(const float4*)&Bm[(size_t)(n0 + n) * K + k0 + k4];
                Bs[k4 + 0][n] = v.x; Bs[k4 + 1][n] = v.y;
                Bs[k4 + 2][n] = v.z; Bs[k4 + 3][n] = v.w;
            }
        }
        __syncthreads();
#pragma unroll
        for (int ks = 0; ks < 4; ks++) {
            int kb = ks * 8;
            unsigned bh[4][2], bl[4][2];
#pragma unroll
            for (int nt = 0; nt < 4; nt++) {
                int col = wn * 32 + nt * 8 + (l >> 2);
                float b0 = Bs[kb + (l & 3)][col];
                float b1 = Bs[kb + (l & 3) + 4][col];
                unsigned u0 = __float_as_uint(b0) & MASK;
                unsigned u1 = __float_as_uint(b1) & MASK;
                bh[nt][0] = u0;
                bh[nt][1] = u1;
                bl[nt][0] = __float_as_uint(b0 - __uint_as_float(u0));
                bl[nt][1] = __float_as_uint(b1 - __uint_as_float(u1));
            }
#pragma unroll
            for (int mt = 0; mt < 2; mt++) {
                int row = wm * 32 + mt * 16 + (l >> 2);
                int ak = kb + (l & 3);
                float a0 = As[ak][row];
                float a1 = As[ak][row + 8];
                float a2 = As[ak + 4][row];
                float a3 = As[ak + 4][row + 8];
                unsigned ah[4], al[4];
                ah[0] = __float_as_uint(a0) & MASK;
                ah[1] = __float_as_uint(a1) & MASK;
                ah[2] = __float_as_uint(a2) & MASK;
                ah[3] = __float_as_uint(a3) & MASK;
                al[0] = __float_as_uint(a0 - __uint_as_float(ah[0]));
                al[1] = __float_as_uint(a1 - __uint_as_float(ah[1]));
                al[2] = __float_as_uint(a2 - __uint_as_float(ah[2]));
                al[3] = __float_as_uint(a3 - __uint_as_float(ah[3]));
#pragma unroll
                for (int nt = 0; nt < 4; nt++) {
                    MMA_TF32(acc[mt][nt], ah, bh[nt]);
                    MMA_TF32(acc[mt][nt], al, bh[nt]);
                    MMA_TF32(acc[mt][nt], ah, bl[nt]);
                }
            }
        }
        __syncthreads();
    }
#pragma unroll
    for (int mt = 0; mt < 2; mt++)
#pragma unroll
        for (int nt = 0; nt < 4; nt++) {
            int r = m0 + wm * 32 + mt * 16 + (l >> 2);
            int c = n0 + wn * 32 + nt * 8 + (l & 3) * 2;
            float b0 = bias ? bias[c] : 0.f;
            float b1 = bias ? bias[c + 1] : 0.f;
            *(float2*)&Cm[(size_t)r * ldc + c] =
                make_float2(acc[mt][nt][0] + b0, acc[mt][nt][1] + b1);
            *(float2*)&Cm[(size_t)(r + 8) * ldc + c] =
                make_float2(acc[mt][nt][2] + b0, acc[mt][nt][3] + b1);
        }
}

// ----------------- LN over rows of 512 (preamble) -----------------
__global__ void k_ln512(float* __restrict__ buf, const float* __restrict__ g,
                        const float* __restrict__ bb) {
    __shared__ float red[8];
    float* p = buf + (size_t)blockIdx.x * 512;
    int tid = threadIdx.x;
    float v0 = p[tid], v1 = p[tid + 256];
    float mean = blockSumAll<8>(v0 + v1, red) * (1.f / 512.f);
    float d0 = v0 - mean, d1 = v1 - mean;
    float var = blockSumAll<8>(d0 * d0 + d1 * d1, red) * (1.f / 512.f);
    float inv = rsqrtf(var + 1e-5f);
    p[tid] = d0 * inv * g[tid] + bb[tid];
    p[tid + 256] = d1 * inv * g[tid + 256] + bb[tid + 256];
}

// ----------------- misc init mega-kernel (preamble) -----------------
__device__ __forceinline__ void transpose_tile(const float* __restrict__ in,
                                               float* __restrict__ out,
                                               int R, int Cc, int tr, int tc) {
    __shared__ float t[32][33];
    int tid = threadIdx.x;
    int lx = tid & 31, ly = tid >> 5;
    int r0 = tr * 32, c0 = tc * 32;
#pragma unroll
    for (int i = ly; i < 32; i += 8)
        t[i][lx] = in[(size_t)(r0 + i) * Cc + c0 + lx];
    __syncthreads();
#pragma unroll
    for (int i = ly; i < 32; i += 8)
        out[(size_t)(c0 + i) * R + r0 + lx] = t[lx][i];
}

__global__ void __launch_bounds__(256) k_misc(
    const float* __restrict__ q_w, const float* __restrict__ q_b,
    const float* __restrict__ attn_in_w, const float* __restrict__ attn_in_b,
    const float* __restrict__ attn_out_b,
    const float* __restrict__ syn_w, const float* __restrict__ syn_b,
    const float* __restrict__ tp1_w, const float* __restrict__ tp2_w,
    const float* __restrict__ sas, const float* __restrict__ st,
    const int* __restrict__ ol, const int* __restrict__ orr,
    const float* __restrict__ da, const float* __restrict__ dco) {
    int blk = blockIdx.x;
    int tid = threadIdx.x;
    if (blk < 64) {
        __shared__ float As[16][65];
        __shared__ float Bs[16][65];
        int m0 = (blk >> 3) * 64, n0 = (blk & 7) * 64;
        int tx = tid % 16, ty = tid / 16;
        float acc[4][4] = {};
        for (int k0 = 0; k0 < 512; k0 += 16) {
#pragma unroll
            for (int p = 0; p < 4; p++) {
                int m = ty + p * 16;
                As[tx][m] = attn_in_w[(size_t)(m0 + m) * 512 + k0 + tx];
                Bs[tx][m] = q_w[(size_t)(n0 + m) * 512 + k0 + tx];
            }
            __syncthreads();
#pragma unroll
            for (int k = 0; k < 16; k++) {
                float a[4], b[4];
#pragma unroll
                for (int i = 0; i < 4; i++) a[i] = As[k][ty * 4 + i];
#pragma unroll
                for (int j = 0; j < 4; j++) b[j] = Bs[k][tx * 4 + j];
#pragma unroll
                for (int i = 0; i < 4; i++)
#pragma unroll
                    for (int j = 0; j < 4; j++) acc[i][j] += a[i] * b[j];
            }
            __syncthreads();
        }
#pragma unroll
        for (int i = 0; i < 4; i++)
#pragma unroll
            for (int j = 0; j < 4; j++)
                g_WqqT[(size_t)(m0 + ty * 4 + i) * 512 + n0 + tx * 4 + j] = acc[i][j];
    } else if (blk < 6464) {
        int tIdx = blk - 64;
        transpose_tile(tp1_w, g_tp1wt, 3200, 2048, tIdx / 64, tIdx % 64);
    } else if (blk < 6720) {
        int tIdx = blk - 6464;
        transpose_tile(tp2_w, g_tp2wt, 128, 2048, tIdx / 64, tIdx % 64);
    } else if (blk < 6722) {
        int e = (blk - 6720) * 256 + tid;
        float s = attn_in_b[e];
        for (int d = 0; d < 512; d++) s += q_b[d] * attn_in_w[(size_t)e * 512 + d];
        g_bqq[e] = s;
    } else if (blk < 6738) {
        int j = (blk - 6722) * 256 + tid;
        float s = syn_b[j];
        for (int e = 0; e < 512; e++) s += attn_out_b[e] * syn_w[(size_t)e * 4096 + j];
        g_synb2[j] = s;
    } else if (blk < 6994) {
        int i = (blk - 6738) * 256 + tid;
        int d = i & 2047;
        g_act[1][i] = sas[d];
#pragma unroll
        for (int s = 0; s < 25; s++) g_trace[(size_t)i * 25 + s] = st[d * 25 + s];
    } else {
        int i = (blk - 6994) * 256 + tid;
        int n = i & 511;
        g_daa[0][i] = 0.f;
        g_dba[0][i] = 0.f;
        g_dao[0][i] = sas[ol[n]] * sas[orr[n]];
        g_dbo[0][i] = 1.f;
        if (i < 512) {
            g_ra[i] = expf(-fminf(fmaxf(da[i], 0.f), 15.f));
            g_ro[i] = expf(-fminf(fmaxf(dco[i], 0.f), 15.f));
        }
    }
}

// ----------------- loop phase 1: syncA + q + attention -----------------
__global__ void __launch_bounds__(256) k_phase1(const int* __restrict__ il,
                                                const int* __restrict__ ir, int p) {
    int b = blockIdx.x >> 3, h = blockIdx.x & 7;
    __shared__ float sa[512];
    __shared__ float qh[64];
    __shared__ float pr[256];
    __shared__ float red[8];
    __shared__ float av[4][64];
    int tid = threadIdx.x;
    const float* act = g_act[1 - p];
#pragma unroll
    for (int r = 0; r < 2; r++) {
        int n = tid + r * 256;
        float ra = g_ra[n];
        float prod = act[b * 2048 + il[n]] * act[b * 2048 + ir[n]];
        float daa = ra * g_daa[p][b * 512 + n] + prod;
        float dba = ra * g_dba[p][b * 512 + n] + 1.f;
        if (h == 0) {
            g_daa[1 - p][b * 512 + n] = daa;
            g_dba[1 - p][b * 512 + n] = dba;
        }
        sa[n] = daa * rsqrtf(dba);
    }
    __syncthreads();
    {
        int e = tid >> 2, qd = tid & 3;
        const float* wr = g_WqqT + (size_t)(h * 64 + e) * 512 + qd * 128;
        const float* sap = sa + qd * 128;
        float acc = 0.f;
#pragma unroll
        for (int k = 0; k < 128; k += 4) {
            float4 w = *(const float4*)&wr[k];
            acc += sap[k] * w.x + sap[k + 1] * w.y + sap[k + 2] * w.z + sap[k + 3] * w.w;
        }
        acc += __shfl_down_sync(0xffffffffu, acc, 2);
        acc += __shfl_down_sync(0xffffffffu, acc, 1);
        if (qd == 0) qh[e] = acc + g_bqq[h * 64 + e];
    }
    __syncthreads();
    const float* Kp = g_KV + ((size_t)(b * 256 + tid)) * 1024 + h * 64;
    float sc = 0.f;
#pragma unroll
    for (int d4 = 0; d4 < 64; d4 += 4) {
        float4 kvv = *(const float4*)&Kp[d4];
        sc += qh[d4] * kvv.x + qh[d4 + 1] * kvv.y + qh[d4 + 2] * kvv.z + qh[d4 + 3] * kvv.w;
    }
    sc *= 0.125f;
    float mall = blockMaxAll<8>(sc, red);
    float e1 = expf(sc - mall);
    float ssum = blockSumAll<8>(e1, red);
    pr[tid] = e1 / ssum;
    __syncthreads();
    int dd = tid & 63, qq = tid >> 6;
    const float* Vp = g_KV + ((size_t)(b * 256 + qq * 64)) * 1024 + 512 + h * 64 + dd;
    float acc = 0.f;
#pragma unroll 8
    for (int j = 0; j < 64; j++) acc += pr[qq * 64 + j] * Vp[(size_t)j * 1024];
    av[qq][dd] = acc;
    __syncthreads();
    if (tid < 64)
        g_attn[b * 512 + h * 64 + tid] = av[0][tid] + av[1][tid] + av[2][tid] + av[3][tid];
}

// ----------------- loop phase 2: fp32x2 syn GEMM, split-K x16 (R13 geometry) -----------------
__global__ void __launch_bounds__(256) k_syngemm(const float* __restrict__ syn_w, int p) {
    __shared__ float As[32 * 32];
    int tid = threadIdx.x;
    int nt = tid & 31, bt = tid >> 5;
    int n0 = blockIdx.x * 128;
    int kc = blockIdx.y;
    const float* act = g_act[1 - p];
    unsigned long long accp[4][2] = {};
    for (int ks = 0; ks < 160; ks += 32) {
        int k0 = kc * 160 + ks;
        __syncthreads();
#pragma unroll
        for (int r = 0; r < 4; r++) {
            int idx = tid + r * 256;
            int kk = idx >> 5, b = idx & 31;
            int k = k0 + kk;
            As[kk * 32 + b] = (k < 512) ? g_attn[b * 512 + k] : act[b * 2048 + (k - 512)];
        }
        __syncthreads();
        const float* Wp = (k0 < 512) ? (g_Was + (size_t)k0 * 4096 + n0)
                                     : (syn_w + (size_t)k0 * 4096 + n0);
#pragma unroll 8
        for (int kk = 0; kk < 32; kk++) {
            float4 a = *(const float4*)&As[kk * 32 + bt * 4];
            ulonglong2 w = *(const ulonglong2*)&Wp[(size_t)kk * 4096 + nt * 4];
            float av[4] = {a.x, a.y, a.z, a.w};
#pragma unroll
            for (int bi = 0; bi < 4; bi++) {
                unsigned long long ap;
                PACK2(ap, av[bi]);
                FMA2(accp[bi][0], ap, w.x);
                FMA2(accp[bi][1], ap, w.y);
            }
        }
    }
#pragma unroll
    for (int bi = 0; bi < 4; bi++) {
        int b = bt * 4 + bi;
        float* dst = g_synp + ((size_t)kc * 32 + b) * 4096 + n0;
        ulonglong2 ov;
        ov.x = accp[bi][0];
        ov.y = accp[bi][1];
        *(ulonglong2*)&dst[nt * 4] = ov;
    }
}

// ----------------- loop phase 3: reduce + GLU + LN + trace -----------------
__global__ void __launch_bounds__(1024) k_phase3(const float* __restrict__ lng,
                                                 const float* __restrict__ lnb, int wslot) {
    int b = blockIdx.x, tid = threadIdx.x;
    __shared__ float red[32];
    float v[2];
    float s = 0.f;
#pragma unroll
    for (int q = 0; q < 2; q++) {
        int jj = tid + q * 1024;
        float a = g_synb2[jj], gg = g_synb2[jj + 2048];
#pragma unroll
        for (int c = 0; c < SYN_KC; c++) {
            a += g_synp[((size_t)c * 32 + b) * 4096 + jj];
            gg += g_synp[((size_t)c * 32 + b) * 4096 + jj + 2048];
        }
        v[q] = a * sigm(gg);
        s += v[q];
    }
    float mean = blockSumAll<32>(s, red) * (1.f / 2048.f);
    float s2 = 0.f;
#pragma unroll
    for (int q = 0; q < 2; q++) {
        float d = v[q] - mean;
        s2 += d * d;
    }
    float var = blockSumAll<32>(s2, red) * (1.f / 2048.f);
    float inv = rsqrtf(var + 1e-5f);
#pragma unroll
    for (int q = 0; q < 2; q++) {
        int jj = tid + q * 1024;
        float st = (v[q] - mean) * inv * lng[jj] + lnb[jj];
        g_trace[((size_t)b * 2048 + jj) * 25 + wslot] = st;
    }
}

// ----------------- loop phase 4: per-neuron NLM (fp32x2 inner loop) -----------------
__global__ void __launch_bounds__(256) k_nlm(const float* __restrict__ tp1b,
                                             const float* __restrict__ tp2b,
                                             int wslot, int p) {
    int d = blockIdx.x;
    __shared__ float w1s[3200];
    __shared__ float b1s[128];
    __shared__ float w2s[128];
    __shared__ float b2s[2];
    __shared__ float ts[32 * 25];
    __shared__ float red[8][32][2];
    int tid = threadIdx.x;
    {
        const float4* src = (const float4*)(g_tp1wt + (size_t)d * 3200);
        float4* dst = (float4*)w1s;
        for (int i = tid; i < 800; i += 256) dst[i] = src[i];
    }
    if (tid < 128) {
        b1s[tid] = tp1b[d * 128 + tid];
        w2s[tid] = g_tp2wt[d * 128 + tid];
    }
    if (tid < 2) b2s[tid] = tp2b[d * 2 + tid];
    for (int i = tid; i < 800; i += 256) {
        int b = i / 25, m = i % 25;
        int slot = wslot + 1 + m;
        if (slot >= 25) slot -= 25;
        ts[b * 25 + m] = g_trace[((size_t)b * 2048 + d) * 25 + slot];
    }
    __syncthreads();
    int lane = tid & 31;
    int wi = tid >> 5;
    int h0 = wi * 8;
    unsigned long long apk[4] = {}, gpk[4] = {};
#pragma unroll
    for (int m = 0; m < 25; m++) {
        float tr = ts[lane * 25 + m];
        unsigned long long trp;
        PACK2(trp, tr);
        ulonglong2 wa0 = *(const ulonglong2*)&w1s[m * 128 + h0];
        ulonglong2 wa1 = *(const ulonglong2*)&w1s[m * 128 + h0 + 4];
        ulonglong2 wg0 = *(const ulonglong2*)&w1s[m * 128 + h0 + 64];
        ulonglong2 wg1 = *(const ulonglong2*)&w1s[m * 128 + h0 + 68];
        FMA2(apk[0], trp, wa0.x);
        FMA2(apk[1], trp, wa0.y);
        FMA2(apk[2], trp, wa1.x);
        FMA2(apk[3], trp, wa1.y);
        FMA2(gpk[0], trp, wg0.x);
        FMA2(gpk[1], trp, wg0.y);
        FMA2(gpk[2], trp, wg1.x);
        FMA2(gpk[3], trp, wg1.y);
    }
    float a[8], gg[8];
#pragma unroll
    for (int j = 0; j < 4; j++) {
        UNPACK2(a[2 * j], a[2 * j + 1], apk[j]);
        UNPACK2(gg[2 * j], gg[2 * j + 1], gpk[j]);
    }
    float p0 = 0.f, p1 = 0.f;
#pragma unroll
    for (int j = 0; j < 8; j++) {
        float hv = (a[j] + b1s[h0 + j]) * sigm(gg[j] + b1s[h0 + 64 + j]);
        p0 += hv * w2s[(h0 + j) * 2];
        p1 += hv * w2s[(h0 + j) * 2 + 1];
    }
    red[wi][lane][0] = p0;
    red[wi][lane][1] = p1;
    __syncthreads();
    if (wi == 0) {
        float z0 = b2s[0], z1 = b2s[1];
#pragma unroll
        for (int k = 0; k < 8; k++) {
            z0 += red[k][lane][0];
            z1 += red[k][lane][1];
        }
        g_act[p][(size_t)lane * 2048 + d] = z0 * sigm(z1);
    }
}

// ----------------- out branch: syncO + out GEMM -----------------
__global__ void __launch_bounds__(256) k_outgemm(
    const float* __restrict__ out_w, const float* __restrict__ out_b,
    const int* __restrict__ il, const int* __restrict__ ir,
    float* __restrict__ dout, int t) {
    int b = blockIdx.y, oc = blockIdx.x;
    int tid = threadIdx.x;
    __shared__ float so[512];
    int p = t & 1;
    const float* act = g_act[p];
    for (int i = tid; i < 512; i += 256) {
        int n = i;
        float ro = g_ro[n];
        float prod = act[b * 2048 + il[n]] * act[b * 2048 + ir[n]];
        float dao = ro * g_dao[p][b * 512 + n] + prod;
        float dbo = ro * g_dbo[p][b * 512 + n] + 1.f;
        float sov = dao * rsqrtf(dbo);
        if (oc == 0) {
            g_dao[1 - p][b * 512 + n] = dao;
            g_dbo[1 - p][b * 512 + n] = dbo;
            if (t == 24) dout[800000 + 1600 + (size_t)b * 512 + n] = sov;
        }
        so[n] = sov;
    }
    __syncthreads();
    if (tid < 250) {
        int o = oc * 250 + tid;
        float acc = out_b[o];
#pragma unroll 4
        for (int n = 0; n < 512; n++) acc += so[n] * out_w[(size_t)n * 1000 + o];
        g_pred[b * 1000 + o] = acc;
        dout[(size_t)b * 25000 + (size_t)o * 25 + t] = acc;
    }
}

__global__ void k_entropy(float* __restrict__ dout, int t) {
    int b = blockIdx.x, tid = threadIdx.x;
    __shared__ float red[8];
    float mx = -3.4e38f;
    for (int o = tid; o < 1000; o += 256) mx = fmaxf(mx, g_pred[b * 1000 + o]);
    mx = blockMaxAll<8>(mx, red);
    float s = 0.f;
    for (int o = tid; o < 1000; o += 256) s += expf(g_pred[b * 1000 + o] - mx);
    s = blockSumAll<8>(s, red);
    float lse = mx + logf(s);
    float s2 = 0.f;
    for (int o = tid; o < 1000; o += 256) {
        float v = g_pred[b * 1000 + o] - lse;
        s2 += expf(v) * v;
    }
    s2 = blockSumAll<8>(s2, red);
    if (tid == 0) {
        float ne = -s2 / logf(1000.f);
        dout[800000 + (size_t)b * 50 + t] = ne;
        dout[800000 + (size_t)b * 50 + 25 + t] = 1.f - ne;
    }
}

// ----------------- host launcher -----------------
extern "C" void kernel_launch(void* const* d_in, const int* in_sizes, int n_in,
                              void* d_out, int out_size) {
    const float* x = (const float*)d_in[0];
    const float* kv_w = (const float*)d_in[1];
    const float* kv_b = (const float*)d_in[2];
    const float* kv_ln_g = (const float*)d_in[3];
    const float* kv_ln_b = (const float*)d_in[4];
    const float* q_w = (const float*)d_in[5];
    const float* q_b = (const float*)d_in[6];
    const float* attn_in_w = (const float*)d_in[7];
    const float* attn_in_b = (const float*)d_in[8];
    const float* attn_out_w = (const float*)d_in[9];
    const float* attn_out_b = (const float*)d_in[10];
    const float* syn_w = (const float*)d_in[11];
    const float* syn_b = (const float*)d_in[12];
    const float* syn_ln_g = (const float*)d_in[13];
    const float* syn_ln_b = (const float*)d_in[14];
    const float* tp1_w = (const float*)d_in[15];
    const float* tp1_b = (const float*)d_in[16];
    const float* tp2_w = (const float*)d_in[17];
    const float* tp2_b = (const float*)d_in[18];
    const float* sas = (const float*)d_in[19];
    const float* start_trace = (const float*)d_in[20];
    const float* decay_action = (const float*)d_in[21];
    const float* decay_out = (const float*)d_in[22];
    const float* out_w = (const float*)d_in[23];
    const float* out_b = (const float*)d_in[24];
    const int* idx_al = (const int*)d_in[25];
    const int* idx_ar = (const int*)d_in[26];
    const int* idx_ol = (const int*)d_in[27];
    const int* idx_or = (const int*)d_in[28];
    float* dout = (float*)d_out;

    float *p_kv, *p_KV, *p_Was;
    cudaGetSymbolAddress((void**)&p_kv, g_kv);
    cudaGetSymbolAddress((void**)&p_KV, g_KV);
    cudaGetSymbolAddress((void**)&p_Was, g_Was);

    static cudaStream_t s2 = nullptr;
    static cudaEvent_t evF = nullptr, evP = nullptr, evI = nullptr, evJ = nullptr;
    if (!s2) {
        cudaStreamCreateWithFlags(&s2, cudaStreamNonBlocking);
        cudaEventCreateWithFlags(&evF, cudaEventDisableTiming);
        cudaEventCreateWithFlags(&evP, cudaEventDisableTiming);
        cudaEventCreateWithFlags(&evI, cudaEventDisableTiming);
        cudaEventCreateWithFlags(&evJ, cudaEventDisableTiming);
    }

    // ---- preamble: fork tf32 Was-fold + misc onto s2; tf32 kv chain on main ----
    cudaEventRecord(evF, 0);
    cudaStreamWaitEvent(s2, evF, 0);
    k_tgemm<<<dim3(32, 8), 256, 0, s2>>>(attn_out_w, syn_w, (const float*)nullptr,
                                         p_Was, 512, 4096, 512, 4096, 1, 0);
    k_misc<<<7058, 256, 0, s2>>>(q_w, q_b, attn_in_w, attn_in_b, attn_out_b, syn_w, syn_b,
                                 tp1_w, tp2_w, sas, start_trace, idx_ol, idx_or,
                                 decay_action, decay_out);
    cudaEventRecord(evP, s2);

    k_tgemm<<<dim3(4, 128), 256>>>(x, kv_w, kv_b, p_kv, 8192, 512, 512, 512, 2, 0);
    k_ln512<<<8192, 256>>>(p_kv, kv_ln_g, kv_ln_b);
    k_tgemm<<<dim3(8, 128), 256>>>(p_kv, attn_in_w + 512 * 512, attn_in_b + 512,
                                   p_KV, 8192, 1024, 512, 1024, 0, 1);
    cudaStreamWaitEvent(0, evP, 0);

    // ---- 25 iterations: R13 loop structure (4 main nodes, forward fork to s2) ----
    for (int t = 0; t < NITER; t++) {
        int p = t & 1;
        k_phase1<<<256, 256>>>(idx_al, idx_ar, p);
        k_syngemm<<<dim3(32, SYN_KC), 256>>>(syn_w, p);
        k_phase3<<<32, 1024>>>(syn_ln_g, syn_ln_b, t);
        k_nlm<<<2048, 256>>>(tp1_b, tp2_b, t, p);
        cudaEventRecord(evI, 0);
        cudaStreamWaitEvent(s2, evI, 0);
        k_outgemm<<<dim3(4, 32), 256, 0, s2>>>(out_w, out_b, idx_ol, idx_or, dout, t);
        k_entropy<<<32, 256, 0, s2>>>(dout, t);
    }
    cudaEventRecord(evJ, s2);
    cudaStreamWaitEvent(0, evJ, 0);
}